// round 16
// baseline (speedup 1.0000x reference)
#include <cuda_runtime.h>
#include <cuda_bf16.h>
#include <cuda_fp16.h>
#include <math.h>

// Problem constants
#define BATCH  2
#define LSEQ   2304          // 48*48
#define CDIM   512
#define NH     8
#define NKV    4
#define HD     64
#define BL     (BATCH*LSEQ)  // 4608
#define QKVD   1024          // fused q(512) | k(256) | v(256)
#define NT     (LSEQ/64)     // 36 key tiles

// Scratch (device globals; no allocation allowed)
__device__ float g_qkv[(size_t)BL * QKVD];
__device__ float g_vt[(size_t)BATCH * NKV * HD * LSEQ];   // [b][kvh][dim][key]
__device__ float g_attn[(size_t)BL * CDIM];
__device__ float g_cos[(size_t)LSEQ * 32];
__device__ float g_sin[(size_t)LSEQ * 32];

// ---------------------------------------------------------------------------
// tf32 / mma / ldmatrix / cp.async helpers
// ---------------------------------------------------------------------------
__device__ __forceinline__ unsigned f2tf32(float x) {
    unsigned r;
    asm("cvt.rna.tf32.f32 %0, %1;" : "=r"(r) : "f"(x));
    return r;
}
__device__ __forceinline__ float f2tf32f(float x) {
    return __uint_as_float(f2tf32(x));
}

__device__ __forceinline__ void mma_tf32(float c[4], const unsigned a[4],
                                         unsigned b0, unsigned b1) {
    asm volatile(
        "mma.sync.aligned.m16n8k8.row.col.f32.tf32.tf32.f32 "
        "{%0,%1,%2,%3}, {%4,%5,%6,%7}, {%8,%9}, {%0,%1,%2,%3};"
        : "+f"(c[0]), "+f"(c[1]), "+f"(c[2]), "+f"(c[3])
        : "r"(a[0]), "r"(a[1]), "r"(a[2]), "r"(a[3]), "r"(b0), "r"(b1));
}

__device__ __forceinline__ void ldsm4(unsigned r[4], const float* p) {
    unsigned a = (unsigned)__cvta_generic_to_shared(p);
    asm volatile(
        "ldmatrix.sync.aligned.m8n8.x4.shared.b16 {%0,%1,%2,%3}, [%4];"
        : "=r"(r[0]), "=r"(r[1]), "=r"(r[2]), "=r"(r[3]) : "r"(a));
}

__device__ __forceinline__ void cpa16(float* dst, const float* src) {
    unsigned d = (unsigned)__cvta_generic_to_shared(dst);
    asm volatile("cp.async.cg.shared.global [%0], [%1], 16;" :: "r"(d), "l"(src));
}
#define CPA_COMMIT asm volatile("cp.async.commit_group;")
template <int N>
__device__ __forceinline__ void cpa_wait() {
    asm volatile("cp.async.wait_group %0;" :: "n"(N));
}

// Dual exponential via one fp16x2 MUFU op; outputs have <=11-bit significands
// -> exactly tf32-representable (no cvt needed before mma).
__device__ __forceinline__ float2 exp2_h2(float t0, float t1) {
    __half2 h = __floats2half2_rn(t0, t1);
    unsigned u = *(unsigned*)&h;
    asm("ex2.approx.f16x2 %0, %0;" : "+r"(u));
    __half2 r = *(__half2*)&u;
    return __half22float2(r);
}

// ---------------------------------------------------------------------------
// tf32 GEMM tile body — cp.async 3-slot ring, 2-deep prefetch, one barrier
// per k-iter. tf32 rounding at consumption.
// mode: 0 = fp32 store, 1 = tf32-rounded store, 2 = V transposed store.
// ---------------------------------------------------------------------------
#define ALD 20
#define BLD 72
#define GA_TILE (64 * ALD)
#define GB_TILE (16 * BLD)

__device__ __forceinline__ void gemm_body(
    const float* __restrict__ A, int lda,
    const float* __restrict__ B, int ldb,
    float* __restrict__ C, int ldc,
    int K, int bR, int bColB, int bColC, int mode)
{
    __shared__ float As[3][GA_TILE];
    __shared__ float Bs[3][GB_TILE];

    int tid  = threadIdx.x;
    int lane = tid & 31;
    int warp = tid >> 5;
    int wm = warp >> 1, wn = warp & 1;
    int gid = lane >> 2, q4 = lane & 3;
    int lm = lane >> 3, lr = lane & 7;

    float acc[2][4][4];
#pragma unroll
    for (int mi = 0; mi < 2; mi++)
#pragma unroll
        for (int nj = 0; nj < 4; nj++)
#pragma unroll
            for (int e = 0; e < 4; e++) acc[mi][nj][e] = 0.f;

#define GEMM_LOAD(slot, k0)                                                   \
    {                                                                         \
        _Pragma("unroll")                                                     \
        for (int i = 0; i < 2; i++) {                                         \
            int ci = tid + 128 * i;                                           \
            int r = ci >> 2, c4 = (ci & 3) * 4;                               \
            cpa16(&As[slot][r * ALD + c4],                                    \
                  &A[(size_t)(bR + r) * lda + (k0) + c4]);                    \
            int rb = ci >> 4, cb4 = (ci & 15) * 4;                            \
            cpa16(&Bs[slot][rb * BLD + cb4],                                  \
                  &B[(size_t)((k0) + rb) * ldb + bColB + cb4]);               \
        }                                                                     \
    }

    GEMM_LOAD(0, 0);  CPA_COMMIT;
    GEMM_LOAD(1, 16); CPA_COMMIT;

    int slot = 0;
    for (int k0 = 0; k0 < K; k0 += 16) {
        cpa_wait<1>();
        __syncthreads();

        if (k0 + 32 < K) {
            int ns = slot + 2; if (ns >= 3) ns -= 3;
            GEMM_LOAD(ns, k0 + 32);
        }
        CPA_COMMIT;

        const float* Ap = As[slot];
        const float* Bp = Bs[slot];
#pragma unroll
        for (int t = 0; t < 2; t++) {
            unsigned af[2][4];
#pragma unroll
            for (int mi = 0; mi < 2; mi++) {
                unsigned raw[4];
                ldsm4(raw, &Ap[(wm * 32 + mi * 16 + ((lm & 1) ? 8 : 0) + lr) * ALD
                               + t * 8 + ((lm & 2) ? 4 : 0)]);
#pragma unroll
                for (int e = 0; e < 4; e++)
                    af[mi][e] = f2tf32(__uint_as_float(raw[e]));
            }
#pragma unroll
            for (int nj = 0; nj < 4; nj++) {
                int cb = wn * 32 + nj * 8 + gid;
                unsigned b0 = f2tf32(Bp[(t * 8 + q4) * BLD + cb]);
                unsigned b1 = f2tf32(Bp[(t * 8 + 4 + q4) * BLD + cb]);
#pragma unroll
                for (int mi = 0; mi < 2; mi++)
                    mma_tf32(acc[mi][nj], af[mi], b0, b1);
            }
        }
        slot = slot + 1; if (slot >= 3) slot -= 3;
    }

    if (mode == 2) {
        float* VT = C;
#pragma unroll
        for (int mi = 0; mi < 2; mi++) {
#pragma unroll
            for (int nj = 0; nj < 4; nj++) {
#pragma unroll
                for (int e = 0; e < 4; e++) {
                    int R = bR + wm * 32 + mi * 16 + gid + (e >> 1) * 8;
                    int c = bColC + wn * 32 + nj * 8 + 2 * q4 + (e & 1);
                    int vcol = c - 768;
                    int kvh = vcol >> 6, dim = vcol & 63;
                    int bb = R >= LSEQ;
                    int key = R - bb * LSEQ;
                    VT[(size_t)((bb * NKV + kvh) * HD + dim) * LSEQ + key] =
                        f2tf32f(acc[mi][nj][e]);
                }
            }
        }
        return;
    }

#pragma unroll
    for (int mi = 0; mi < 2; mi++) {
        int r0 = bR + wm * 32 + mi * 16 + gid;
#pragma unroll
        for (int nj = 0; nj < 4; nj++) {
            int c = bColC + wn * 32 + nj * 8 + 2 * q4;
            if (mode == 1) {
                *(float2*)&C[(size_t)r0 * ldc + c] =
                    make_float2(f2tf32f(acc[mi][nj][0]), f2tf32f(acc[mi][nj][1]));
                *(float2*)&C[(size_t)(r0 + 8) * ldc + c] =
                    make_float2(f2tf32f(acc[mi][nj][2]), f2tf32f(acc[mi][nj][3]));
            } else {
                *(float2*)&C[(size_t)r0 * ldc + c] =
                    make_float2(acc[mi][nj][0], acc[mi][nj][1]);
                *(float2*)&C[(size_t)(r0 + 8) * ldc + c] =
                    make_float2(acc[mi][nj][2], acc[mi][nj][3]);
            }
        }
    }
}

__global__ __launch_bounds__(128) void gemm_qkv_kernel(
    const float* __restrict__ x, const float* __restrict__ wq,
    const float* __restrict__ wk, const float* __restrict__ wv,
    float* __restrict__ qkv, float* __restrict__ vt)
{
    int bC = blockIdx.x * 64;
    int bR = blockIdx.y * 64;
    if (bC < 512)
        gemm_body(x, CDIM, wq, 512, qkv, QKVD, CDIM, bR, bC, bC, 1);
    else if (bC < 768)
        gemm_body(x, CDIM, wk, 256, qkv, QKVD, CDIM, bR, bC - 512, bC, 1);
    else
        gemm_body(x, CDIM, wv, 256, vt, 0, CDIM, bR, bC - 768, bC, 2);
}

__global__ __launch_bounds__(128) void gemm_out_kernel(
    const float* __restrict__ A, const float* __restrict__ B,
    float* __restrict__ C)
{
    gemm_body(A, CDIM, B, CDIM, C, CDIM, CDIM, blockIdx.y * 64,
              blockIdx.x * 64, blockIdx.x * 64, 0);
}

// ---------------------------------------------------------------------------
// RoPE trig table
// ---------------------------------------------------------------------------
__global__ __launch_bounds__(32) void trig_kernel() {
    int pos = blockIdx.x, f = threadIdx.x;
    float inv_freq = powf(10000.0f, -(float)f / 32.0f);
    float s, c;
    sincosf((float)pos * inv_freq, &s, &c);
    g_cos[pos * 32 + f] = c;
    g_sin[pos * 32 + f] = s;
}

// ---------------------------------------------------------------------------
// Fused RMSNorm + RoPE. tf32-rounded output; q scaled by 1/8 (exact).
// ---------------------------------------------------------------------------
__global__ __launch_bounds__(256) void norm_rope_kernel(
    float* __restrict__ qkv, const float* __restrict__ qw,
    const float* __restrict__ kw)
{
    int u = blockIdx.x * 8 + (threadIdx.x >> 5);
    int lane = threadIdx.x & 31;
    int row = u / 12;
    int j   = u % 12;
    if (row >= BL) return;

    float* p; const float* w; float osc;
    if (j < 8) { p = qkv + (size_t)row * QKVD + j * HD;             w = qw; osc = 0.125f; }
    else       { p = qkv + (size_t)row * QKVD + 512 + (j - 8) * HD; w = kw; osc = 1.0f; }
    int pos = row % LSEQ;

    float x1 = p[lane], x2 = p[lane + 32];
    float ss = x1 * x1 + x2 * x2;
#pragma unroll
    for (int m = 16; m > 0; m >>= 1)
        ss += __shfl_xor_sync(0xffffffffu, ss, m);
    float inv = rsqrtf(ss * (1.0f / HD) + 1e-6f);
    float n1 = x1 * inv * w[lane];
    float n2 = x2 * inv * w[lane + 32];

    float c = g_cos[pos * 32 + lane];
    float s = g_sin[pos * 32 + lane];
    p[lane]      = f2tf32f((n1 * c - n2 * s) * osc);
    p[lane + 32] = f2tf32f((n1 * s + n2 * c) * osc);
}

// ---------------------------------------------------------------------------
// Flash attention, tf32, dual-ex2 softmax, register-P, 3-deep K/V ring,
// ONE barrier per tile. 256 THREADS / 8 WARPS: warp = (wq4: 16-query slice,
// wk2: key half) -> halved per-warp state, 4 warps/SMSP at 2 CTAs/SM.
// ---------------------------------------------------------------------------
#define SLD 68
#define TILE (64 * SLD)
#define ATTN_SMEM ((6 * TILE + 128) * sizeof(float))
#define L2E 1.4426950408889634f

__device__ __forceinline__ void load_k256(float* Ks, const float* kbase,
                                          int k0, int tid)
{
#pragma unroll
    for (int i = 0; i < 4; i++) {
        int ci = tid + 256 * i;
        int r = ci >> 4, c4 = (ci & 15) * 4;
        cpa16(&Ks[r * SLD + c4], &kbase[(size_t)(k0 + r) * QKVD + c4]);
    }
}
__device__ __forceinline__ void load_v256(float* Vt, const float* vtb,
                                          int k0, int tid)
{
#pragma unroll
    for (int i = 0; i < 4; i++) {
        int ci = tid + 256 * i;
        int r = ci >> 4, c4 = (ci & 15) * 4;
        cpa16(&Vt[r * SLD + c4], &vtb[(size_t)r * LSEQ + k0 + c4]);
    }
}

__global__ __launch_bounds__(256, 2) void attn_kernel(
    const float* __restrict__ QKV, const float* __restrict__ VT,
    float* __restrict__ O)
{
    extern __shared__ float sm[];
    float* Kb[3] = { sm, sm + TILE, sm + 2 * TILE };
    float* Vb[3] = { sm + 3 * TILE, sm + 4 * TILE, sm + 5 * TILE };
    float* lsh = sm + 6 * TILE;    // [2][64] key-half l partials

    int tid  = threadIdx.x;
    int lane = tid & 31;
    int warp = tid >> 5;
    int wq4 = warp >> 1;           // 0..3: 16-query slice
    int wk2 = warp & 1;            // key half
    int gid = lane >> 2, q4 = lane & 3;
    int lm = lane >> 3, lr = lane & 7;

    int qt = blockIdx.x, h = blockIdx.y, b = blockIdx.z;
    int kvh = h >> 1;
    int q0  = qt * 64;
    int qb  = wq4 * 16;

    const float* qbase = QKV + (size_t)(b * LSEQ) * QKVD + h * HD;
    const float* kbase = QKV + (size_t)(b * LSEQ) * QKVD + 512 + kvh * HD;
    const float* vtb   = VT + (size_t)((b * NKV + kvh) * HD) * LSEQ;

    // Prologue: {K0,V0} + {Q -> Kb[2]}
    load_k256(Kb[0], kbase, 0, tid);
    load_v256(Vb[0], vtb, 0, tid);
#pragma unroll
    for (int i = 0; i < 4; i++) {
        int ci = tid + 256 * i;
        int r = ci >> 4, c4 = (ci & 15) * 4;
        cpa16(&Kb[2][r * SLD + c4], &qbase[(size_t)(q0 + r) * QKVD + c4]);
    }
    CPA_COMMIT;
    cpa_wait<0>();
    __syncthreads();

    // Q fragments (one 16-row m-tile per warp)
    unsigned qf[8][4];
#pragma unroll
    for (int t = 0; t < 8; t++)
        ldsm4(qf[t], &Kb[2][(qb + ((lm & 1) ? 8 : 0) + lr) * SLD
                            + t * 8 + ((lm & 2) ? 4 : 0)]);
    __syncthreads();

    // Issue tile 1
    load_k256(Kb[1], kbase, 64, tid);
    load_v256(Vb[1], vtb, 64, tid);
    CPA_COMMIT;

    float oacc[8][4];
#pragma unroll
    for (int j = 0; j < 8; j++)
#pragma unroll
        for (int e = 0; e < 4; e++) oacc[j][e] = 0.f;
    float lacc[2] = {0.f, 0.f};

    int src0 = (lane & ~3) | (q4 >> 1);
    int src1 = src0 + 2;
    bool odd = q4 & 1;

    int slot = 0;
    for (int it = 0; it < NT; it++) {
        cpa_wait<1>();
        __syncthreads();

        if (it + 2 < NT) {
            int ns = (slot + 2) % 3;
            load_k256(Kb[ns], kbase, (it + 2) * 64, tid);
            load_v256(Vb[ns], vtb, (it + 2) * 64, tid);
        }
        CPA_COMMIT;

        const float* Ks = Kb[slot];
        const float* Vt = Vb[slot];

        // --- S = Q @ K^T : this warp's 16q x 32k ---
        float s[4][4];
#pragma unroll
        for (int j = 0; j < 4; j++)
#pragma unroll
            for (int e = 0; e < 4; e++) s[j][e] = 0.f;
#pragma unroll
        for (int t4 = 0; t4 < 4; t4++) {
#pragma unroll
            for (int j = 0; j < 4; j++) {
                unsigned bb[4];
                ldsm4(bb, &Ks[(wk2 * 32 + j * 8 + lr) * SLD + t4 * 16
                              + ((lm & 1) ? 4 : 0) + ((lm & 2) ? 8 : 0)]);
                mma_tf32(s[j], qf[2 * t4],     bb[0], bb[1]);
                mma_tf32(s[j], qf[2 * t4 + 1], bb[2], bb[3]);
            }
        }

        // --- dual-ex2 weights + quad-shuffle transpose + PV ---
#pragma unroll
        for (int t4 = 0; t4 < 2; t4++) {
            unsigned paf[2][4];
#pragma unroll
            for (int jj = 0; jj < 2; jj++) {
                int j = t4 * 2 + jj;
                float2 pA = exp2_h2(s[j][0] * L2E, s[j][1] * L2E);
                float2 pB = exp2_h2(s[j][2] * L2E, s[j][3] * L2E);
                float p0 = pA.x, p1 = pA.y, p2 = pB.x, p3 = pB.y;
                lacc[0] += p0 + p1;
                lacc[1] += p2 + p3;
                float x0 = __shfl_sync(0xffffffffu, p0, src0);
                float x1 = __shfl_sync(0xffffffffu, p1, src0);
                float y0 = __shfl_sync(0xffffffffu, p0, src1);
                float y1 = __shfl_sync(0xffffffffu, p1, src1);
                float z0 = __shfl_sync(0xffffffffu, p2, src0);
                float z1 = __shfl_sync(0xffffffffu, p3, src0);
                float w0 = __shfl_sync(0xffffffffu, p2, src1);
                float w1 = __shfl_sync(0xffffffffu, p3, src1);
                paf[jj][0] = __float_as_uint(odd ? x1 : x0);
                paf[jj][1] = __float_as_uint(odd ? z1 : z0);
                paf[jj][2] = __float_as_uint(odd ? y1 : y0);
                paf[jj][3] = __float_as_uint(odd ? w1 : w0);
            }
#pragma unroll
            for (int j = 0; j < 8; j++) {
                unsigned bb[4];
                ldsm4(bb, &Vt[(j * 8 + lr) * SLD + wk2 * 32 + t4 * 16
                              + ((lm & 1) ? 4 : 0) + ((lm & 2) ? 8 : 0)]);
                mma_tf32(oacc[j], paf[0], bb[0], bb[1]);
                mma_tf32(oacc[j], paf[1], bb[2], bb[3]);
            }
        }

        slot = (slot + 1) % 3;
    }

    // --- l: quad-reduce, publish per key-half ---
#pragma unroll
    for (int ssb = 0; ssb < 2; ssb++) {
        lacc[ssb] += __shfl_xor_sync(0xffffffffu, lacc[ssb], 1);
        lacc[ssb] += __shfl_xor_sync(0xffffffffu, lacc[ssb], 2);
    }
    if (q4 == 0) {
        lsh[wk2 * 64 + qb + gid]     = lacc[0];
        lsh[wk2 * 64 + qb + gid + 8] = lacc[1];
    }
    __syncthreads();   // last tile's reads done before Kb[0] reuse

    // --- O: reduce key-half partials via smem (reuse Kb[0]) ---
    float* Red = Kb[0];
    if (wk2 == 1) {
        int r = qb + gid;
#pragma unroll
        for (int j = 0; j < 8; j++) {
            int c = j * 8 + 2 * q4;
            *(float2*)&Red[r * SLD + c] = make_float2(oacc[j][0], oacc[j][1]);
            *(float2*)&Red[(r + 8) * SLD + c] = make_float2(oacc[j][2], oacc[j][3]);
        }
    }
    __syncthreads();
    if (wk2 == 0) {
        int row0 = qb + gid;
        float il0 = 1.0f / (lsh[row0] + lsh[64 + row0]);
        float il1 = 1.0f / (lsh[row0 + 8] + lsh[64 + row0 + 8]);
        int r = b * LSEQ + q0 + row0;
#pragma unroll
        for (int j = 0; j < 8; j++) {
            int c = j * 8 + 2 * q4;
            float2 o0 = *(float2*)&Red[row0 * SLD + c];
            float2 o1 = *(float2*)&Red[(row0 + 8) * SLD + c];
            int gc = h * HD + c;
            *(float2*)&O[(size_t)r * CDIM + gc] =
                make_float2((oacc[j][0] + o0.x) * il0,
                            (oacc[j][1] + o0.y) * il0);
            *(float2*)&O[(size_t)(r + 8) * CDIM + gc] =
                make_float2((oacc[j][2] + o1.x) * il1,
                            (oacc[j][3] + o1.y) * il1);
        }
    }
}

// ---------------------------------------------------------------------------
extern "C" void kernel_launch(void* const* d_in, const int* in_sizes, int n_in,
                              void* d_out, int out_size)
{
    const float* x   = (const float*)d_in[0];
    const float* wq  = (const float*)d_in[1];
    const float* wk  = (const float*)d_in[2];
    const float* wv  = (const float*)d_in[3];
    const float* wo  = (const float*)d_in[4];
    const float* qnw = (const float*)d_in[5];
    const float* knw = (const float*)d_in[6];
    float* out = (float*)d_out;

    float *pqkv, *pvt, *pa;
    cudaGetSymbolAddress((void**)&pqkv, g_qkv);
    cudaGetSymbolAddress((void**)&pvt, g_vt);
    cudaGetSymbolAddress((void**)&pa, g_attn);

    trig_kernel<<<LSEQ, 32>>>();
    gemm_qkv_kernel<<<dim3(QKVD / 64, BL / 64), 128>>>(x, wq, wk, wv, pqkv, pvt);

    norm_rope_kernel<<<(BL * 12 + 7) / 8, 256>>>(pqkv, qnw, knw);

    cudaFuncSetAttribute(attn_kernel, cudaFuncAttributeMaxDynamicSharedMemorySize,
                         (int)ATTN_SMEM);
    attn_kernel<<<dim3(LSEQ / 64, NH, BATCH), 256, ATTN_SMEM>>>(pqkv, pvt, pa);

    gemm_out_kernel<<<dim3(CDIM / 64, BL / 64), 128>>>(pa, wo, out);
}

// round 17
// speedup vs baseline: 1.2090x; 1.2090x over previous
#include <cuda_runtime.h>
#include <cuda_bf16.h>
#include <cuda_fp16.h>
#include <math.h>

// Problem constants
#define BATCH  2
#define LSEQ   2304          // 48*48
#define CDIM   512
#define NH     8
#define NKV    4
#define HD     64
#define BL     (BATCH*LSEQ)  // 4608
#define QKVD   1024          // fused q(512) | k(256) | v(256)
#define KVDIM  256
#define NT     (LSEQ/64)     // 36 key tiles

// Scratch (device globals; no allocation allowed)
__device__ float  g_qkv[(size_t)BL * QKVD];
__device__ __half g_vh[(size_t)BL * KVDIM];   // V in fp16, [token][kvh*64+dim]
__device__ float  g_attn[(size_t)BL * CDIM];
__device__ float  g_cos[(size_t)LSEQ * 32];
__device__ float  g_sin[(size_t)LSEQ * 32];

// ---------------------------------------------------------------------------
// tf32 / fp16 mma / ldmatrix / cp.async helpers
// ---------------------------------------------------------------------------
__device__ __forceinline__ unsigned f2tf32(float x) {
    unsigned r;
    asm("cvt.rna.tf32.f32 %0, %1;" : "=r"(r) : "f"(x));
    return r;
}
__device__ __forceinline__ float f2tf32f(float x) {
    return __uint_as_float(f2tf32(x));
}

__device__ __forceinline__ void mma_tf32(float c[4], const unsigned a[4],
                                         unsigned b0, unsigned b1) {
    asm volatile(
        "mma.sync.aligned.m16n8k8.row.col.f32.tf32.tf32.f32 "
        "{%0,%1,%2,%3}, {%4,%5,%6,%7}, {%8,%9}, {%0,%1,%2,%3};"
        : "+f"(c[0]), "+f"(c[1]), "+f"(c[2]), "+f"(c[3])
        : "r"(a[0]), "r"(a[1]), "r"(a[2]), "r"(a[3]), "r"(b0), "r"(b1));
}

__device__ __forceinline__ void mma_f16(float c[4], const unsigned a[4],
                                        unsigned b0, unsigned b1) {
    asm volatile(
        "mma.sync.aligned.m16n8k16.row.col.f32.f16.f16.f32 "
        "{%0,%1,%2,%3}, {%4,%5,%6,%7}, {%8,%9}, {%0,%1,%2,%3};"
        : "+f"(c[0]), "+f"(c[1]), "+f"(c[2]), "+f"(c[3])
        : "r"(a[0]), "r"(a[1]), "r"(a[2]), "r"(a[3]), "r"(b0), "r"(b1));
}

__device__ __forceinline__ void ldsm4(unsigned r[4], const float* p) {
    unsigned a = (unsigned)__cvta_generic_to_shared(p);
    asm volatile(
        "ldmatrix.sync.aligned.m8n8.x4.shared.b16 {%0,%1,%2,%3}, [%4];"
        : "=r"(r[0]), "=r"(r[1]), "=r"(r[2]), "=r"(r[3]) : "r"(a));
}

// Transposed fp16 ldmatrix (for row-major [k][n] B operands)
__device__ __forceinline__ void ldsm4t(unsigned r[4], const __half* p) {
    unsigned a = (unsigned)__cvta_generic_to_shared(p);
    asm volatile(
        "ldmatrix.sync.aligned.m8n8.x4.trans.shared.b16 {%0,%1,%2,%3}, [%4];"
        : "=r"(r[0]), "=r"(r[1]), "=r"(r[2]), "=r"(r[3]) : "r"(a));
}

__device__ __forceinline__ void cpa16(void* dst, const void* src) {
    unsigned d = (unsigned)__cvta_generic_to_shared(dst);
    asm volatile("cp.async.cg.shared.global [%0], [%1], 16;" :: "r"(d), "l"(src));
}
#define CPA_COMMIT asm volatile("cp.async.commit_group;")
template <int N>
__device__ __forceinline__ void cpa_wait() {
    asm volatile("cp.async.wait_group %0;" :: "n"(N));
}

// Dual exponential: returns PACKED half2 of 2^t0, 2^t1 (one MUFU op), and the
// float values for the l-sum. Packed result is directly an fp16 mma A operand.
__device__ __forceinline__ unsigned exp2pk(float t0, float t1, float2& f) {
    __half2 h = __floats2half2_rn(t0, t1);
    unsigned u = *(unsigned*)&h;
    asm("ex2.approx.f16x2 %0, %0;" : "+r"(u));
    f = __half22float2(*(__half2*)&u);
    return u;
}

// ---------------------------------------------------------------------------
// tf32 GEMM tile body — cp.async 3-slot ring, 2-deep prefetch, one barrier
// per k-iter. tf32 rounding at consumption.
// mode: 0 = fp32 store, 1 = tf32-rounded store, 2 = V fp16 store to g_vh.
// ---------------------------------------------------------------------------
#define ALD 20
#define BLD 72
#define GA_TILE (64 * ALD)
#define GB_TILE (16 * BLD)

__device__ __forceinline__ void gemm_body(
    const float* __restrict__ A, int lda,
    const float* __restrict__ B, int ldb,
    float* __restrict__ C, int ldc,
    int K, int bR, int bColB, int bColC, int mode, __half* __restrict__ VH)
{
    __shared__ float As[3][GA_TILE];
    __shared__ float Bs[3][GB_TILE];

    int tid  = threadIdx.x;
    int lane = tid & 31;
    int warp = tid >> 5;
    int wm = warp >> 1, wn = warp & 1;
    int gid = lane >> 2, q4 = lane & 3;
    int lm = lane >> 3, lr = lane & 7;

    float acc[2][4][4];
#pragma unroll
    for (int mi = 0; mi < 2; mi++)
#pragma unroll
        for (int nj = 0; nj < 4; nj++)
#pragma unroll
            for (int e = 0; e < 4; e++) acc[mi][nj][e] = 0.f;

#define GEMM_LOAD(slot, k0)                                                   \
    {                                                                         \
        _Pragma("unroll")                                                     \
        for (int i = 0; i < 2; i++) {                                         \
            int ci = tid + 128 * i;                                           \
            int r = ci >> 2, c4 = (ci & 3) * 4;                               \
            cpa16(&As[slot][r * ALD + c4],                                    \
                  &A[(size_t)(bR + r) * lda + (k0) + c4]);                    \
            int rb = ci >> 4, cb4 = (ci & 15) * 4;                            \
            cpa16(&Bs[slot][rb * BLD + cb4],                                  \
                  &B[(size_t)((k0) + rb) * ldb + bColB + cb4]);               \
        }                                                                     \
    }

    GEMM_LOAD(0, 0);  CPA_COMMIT;
    GEMM_LOAD(1, 16); CPA_COMMIT;

    int slot = 0;
    for (int k0 = 0; k0 < K; k0 += 16) {
        cpa_wait<1>();
        __syncthreads();

        if (k0 + 32 < K) {
            int ns = slot + 2; if (ns >= 3) ns -= 3;
            GEMM_LOAD(ns, k0 + 32);
        }
        CPA_COMMIT;

        const float* Ap = As[slot];
        const float* Bp = Bs[slot];
#pragma unroll
        for (int t = 0; t < 2; t++) {
            unsigned af[2][4];
#pragma unroll
            for (int mi = 0; mi < 2; mi++) {
                unsigned raw[4];
                ldsm4(raw, &Ap[(wm * 32 + mi * 16 + ((lm & 1) ? 8 : 0) + lr) * ALD
                               + t * 8 + ((lm & 2) ? 4 : 0)]);
#pragma unroll
                for (int e = 0; e < 4; e++)
                    af[mi][e] = f2tf32(__uint_as_float(raw[e]));
            }
#pragma unroll
            for (int nj = 0; nj < 4; nj++) {
                int cb = wn * 32 + nj * 8 + gid;
                unsigned b0 = f2tf32(Bp[(t * 8 + q4) * BLD + cb]);
                unsigned b1 = f2tf32(Bp[(t * 8 + 4 + q4) * BLD + cb]);
#pragma unroll
                for (int mi = 0; mi < 2; mi++)
                    mma_tf32(acc[mi][nj], af[mi], b0, b1);
            }
        }
        slot = slot + 1; if (slot >= 3) slot -= 3;
    }

    if (mode == 2) {
        // V block: fp16 store (natural [token][kv-col] layout)
#pragma unroll
        for (int mi = 0; mi < 2; mi++) {
            int r0 = bR + wm * 32 + mi * 16 + gid;
#pragma unroll
            for (int nj = 0; nj < 4; nj++) {
                int vc = bColC - 768 + wn * 32 + nj * 8 + 2 * q4;
                __half2 h0 = __floats2half2_rn(acc[mi][nj][0], acc[mi][nj][1]);
                __half2 h1 = __floats2half2_rn(acc[mi][nj][2], acc[mi][nj][3]);
                *(__half2*)&VH[(size_t)r0 * KVDIM + vc] = h0;
                *(__half2*)&VH[(size_t)(r0 + 8) * KVDIM + vc] = h1;
            }
        }
        return;
    }

#pragma unroll
    for (int mi = 0; mi < 2; mi++) {
        int r0 = bR + wm * 32 + mi * 16 + gid;
#pragma unroll
        for (int nj = 0; nj < 4; nj++) {
            int c = bColC + wn * 32 + nj * 8 + 2 * q4;
            if (mode == 1) {
                *(float2*)&C[(size_t)r0 * ldc + c] =
                    make_float2(f2tf32f(acc[mi][nj][0]), f2tf32f(acc[mi][nj][1]));
                *(float2*)&C[(size_t)(r0 + 8) * ldc + c] =
                    make_float2(f2tf32f(acc[mi][nj][2]), f2tf32f(acc[mi][nj][3]));
            } else {
                *(float2*)&C[(size_t)r0 * ldc + c] =
                    make_float2(acc[mi][nj][0], acc[mi][nj][1]);
                *(float2*)&C[(size_t)(r0 + 8) * ldc + c] =
                    make_float2(acc[mi][nj][2], acc[mi][nj][3]);
            }
        }
    }
}

__global__ __launch_bounds__(128) void gemm_qkv_kernel(
    const float* __restrict__ x, const float* __restrict__ wq,
    const float* __restrict__ wk, const float* __restrict__ wv,
    float* __restrict__ qkv, __half* __restrict__ vh)
{
    int bC = blockIdx.x * 64;
    int bR = blockIdx.y * 64;
    if (bC < 512)
        gemm_body(x, CDIM, wq, 512, qkv, QKVD, CDIM, bR, bC, bC, 1, 0);
    else if (bC < 768)
        gemm_body(x, CDIM, wk, 256, qkv, QKVD, CDIM, bR, bC - 512, bC, 1, 0);
    else
        gemm_body(x, CDIM, wv, 256, 0, 0, CDIM, bR, bC - 768, bC, 2, vh);
}

__global__ __launch_bounds__(128) void gemm_out_kernel(
    const float* __restrict__ A, const float* __restrict__ B,
    float* __restrict__ C)
{
    gemm_body(A, CDIM, B, CDIM, C, CDIM, CDIM, blockIdx.y * 64,
              blockIdx.x * 64, blockIdx.x * 64, 0, 0);
}

// ---------------------------------------------------------------------------
// RoPE trig table
// ---------------------------------------------------------------------------
__global__ __launch_bounds__(32) void trig_kernel() {
    int pos = blockIdx.x, f = threadIdx.x;
    float inv_freq = powf(10000.0f, -(float)f / 32.0f);
    float s, c;
    sincosf((float)pos * inv_freq, &s, &c);
    g_cos[pos * 32 + f] = c;
    g_sin[pos * 32 + f] = s;
}

// ---------------------------------------------------------------------------
// Fused RMSNorm + RoPE. tf32-rounded output; q scaled by 1/8 (exact).
// ---------------------------------------------------------------------------
__global__ __launch_bounds__(256) void norm_rope_kernel(
    float* __restrict__ qkv, const float* __restrict__ qw,
    const float* __restrict__ kw)
{
    int u = blockIdx.x * 8 + (threadIdx.x >> 5);
    int lane = threadIdx.x & 31;
    int row = u / 12;
    int j   = u % 12;
    if (row >= BL) return;

    float* p; const float* w; float osc;
    if (j < 8) { p = qkv + (size_t)row * QKVD + j * HD;             w = qw; osc = 0.125f; }
    else       { p = qkv + (size_t)row * QKVD + 512 + (j - 8) * HD; w = kw; osc = 1.0f; }
    int pos = row % LSEQ;

    float x1 = p[lane], x2 = p[lane + 32];
    float ss = x1 * x1 + x2 * x2;
#pragma unroll
    for (int m = 16; m > 0; m >>= 1)
        ss += __shfl_xor_sync(0xffffffffu, ss, m);
    float inv = rsqrtf(ss * (1.0f / HD) + 1e-6f);
    float n1 = x1 * inv * w[lane];
    float n2 = x2 * inv * w[lane + 32];

    float c = g_cos[pos * 32 + lane];
    float s = g_sin[pos * 32 + lane];
    p[lane]      = f2tf32f((n1 * c - n2 * s) * osc);
    p[lane + 32] = f2tf32f((n1 * s + n2 * c) * osc);
}

// ---------------------------------------------------------------------------
// Flash attention. QK: tf32 (fp32 K, register Q). Softmax: dual fp16 ex2,
// shift-free. PV: fp16 mma — the QK C-fragment IS the PV A-fragment when P is
// fp16 (no transpose shuffles), V fp16 via ldmatrix.x4.trans in natural
// [key][dim] layout. 128 threads / 4 warps (32q x 32k each), 3-deep ring,
// one barrier per tile.
// ---------------------------------------------------------------------------
#define SLD 68
#define TILE (64 * SLD)
#define VLD 72                                    // half units per V row
#define VTILEH (64 * VLD)                         // halves per V slot
#define ATTN_SMEM ((3 * TILE + 3 * VTILEH / 2 + 128) * sizeof(float))
#define L2E 1.4426950408889634f

__device__ __forceinline__ void load_k(float* Ks, const float* kbase,
                                       int k0, int tid)
{
#pragma unroll
    for (int i = 0; i < 8; i++) {
        int ci = tid + 128 * i;
        int r = ci >> 4, c4 = (ci & 15) * 4;
        cpa16(&Ks[r * SLD + c4], &kbase[(size_t)(k0 + r) * QKVD + c4]);
    }
}
__device__ __forceinline__ void load_v16(__half* Vs, const __half* vb,
                                         int k0, int tid)
{
#pragma unroll
    for (int i = 0; i < 4; i++) {
        int ci = tid + 128 * i;
        int r = ci >> 3, c8 = (ci & 7) * 8;      // 8 halves = 16B per chunk
        cpa16(&Vs[r * VLD + c8], &vb[(size_t)(k0 + r) * KVDIM + c8]);
    }
}

__global__ __launch_bounds__(128) void attn_kernel(
    const float* __restrict__ QKV, const __half* __restrict__ VH,
    float* __restrict__ O)
{
    extern __shared__ float sm[];
    float* Kb[3] = { sm, sm + TILE, sm + 2 * TILE };
    __half* Vh = (__half*)(sm + 3 * TILE);
    __half* Vb[3] = { Vh, Vh + VTILEH, Vh + 2 * VTILEH };
    float* lsh = sm + 3 * TILE + (3 * VTILEH) / 2;   // [2][64]

    int tid  = threadIdx.x;
    int lane = tid & 31;
    int warp = tid >> 5;
    int wq2 = warp >> 1, wk2 = warp & 1;
    int gid = lane >> 2, q4 = lane & 3;
    int lm = lane >> 3, lr = lane & 7;

    int qt = blockIdx.x, h = blockIdx.y, b = blockIdx.z;
    int kvh = h >> 1;
    int q0  = qt * 64;
    int qb  = wq2 * 32;

    const float* qbase = QKV + (size_t)(b * LSEQ) * QKVD + h * HD;
    const float* kbase = QKV + (size_t)(b * LSEQ) * QKVD + 512 + kvh * HD;
    const __half* vb   = VH + (size_t)(b * LSEQ) * KVDIM + kvh * HD;

    // Prologue: {K0,V0} + {Q -> Kb[2]}
    load_k(Kb[0], kbase, 0, tid);
    load_v16(Vb[0], vb, 0, tid);
#pragma unroll
    for (int i = 0; i < 8; i++) {
        int ci = tid + 128 * i;
        int r = ci >> 4, c4 = (ci & 15) * 4;
        cpa16(&Kb[2][r * SLD + c4], &qbase[(size_t)(q0 + r) * QKVD + c4]);
    }
    CPA_COMMIT;
    cpa_wait<0>();
    __syncthreads();

    // Q fragments from Kb[2]
    unsigned qf[2][8][4];
#pragma unroll
    for (int mi = 0; mi < 2; mi++)
#pragma unroll
        for (int t = 0; t < 8; t++)
            ldsm4(qf[mi][t], &Kb[2][(qb + mi * 16 + ((lm & 1) ? 8 : 0) + lr) * SLD
                                    + t * 8 + ((lm & 2) ? 4 : 0)]);
    __syncthreads();

    // Issue tile 1
    load_k(Kb[1], kbase, 64, tid);
    load_v16(Vb[1], vb, 64, tid);
    CPA_COMMIT;

    float oacc[2][8][4];
#pragma unroll
    for (int mi = 0; mi < 2; mi++)
#pragma unroll
        for (int j = 0; j < 8; j++)
#pragma unroll
            for (int e = 0; e < 4; e++) oacc[mi][j][e] = 0.f;
    float lacc[2][2] = {{0.f, 0.f}, {0.f, 0.f}};

    int slot = 0;
    for (int it = 0; it < NT; it++) {
        cpa_wait<1>();
        __syncthreads();

        if (it + 2 < NT) {
            int ns = (slot + 2) % 3;
            load_k(Kb[ns], kbase, (it + 2) * 64, tid);
            load_v16(Vb[ns], vb, (it + 2) * 64, tid);
        }
        CPA_COMMIT;

        const float* Ks = Kb[slot];
        const __half* Vt = Vb[slot];

        // --- S = Q @ K^T : this warp's 32q x 32k (tf32) ---
        float s[2][4][4];
#pragma unroll
        for (int mi = 0; mi < 2; mi++)
#pragma unroll
            for (int j = 0; j < 4; j++)
#pragma unroll
                for (int e = 0; e < 4; e++) s[mi][j][e] = 0.f;
#pragma unroll
        for (int t4 = 0; t4 < 4; t4++) {
#pragma unroll
            for (int j = 0; j < 4; j++) {
                unsigned bb[4];
                ldsm4(bb, &Ks[(wk2 * 32 + j * 8 + lr) * SLD + t4 * 16
                              + ((lm & 1) ? 4 : 0) + ((lm & 2) ? 8 : 0)]);
#pragma unroll
                for (int mi = 0; mi < 2; mi++) {
                    mma_tf32(s[mi][j], qf[mi][2 * t4],     bb[0], bb[1]);
                    mma_tf32(s[mi][j], qf[mi][2 * t4 + 1], bb[2], bb[3]);
                }
            }
        }

        // --- dual-ex2 -> packed fp16 P (C-frag == A-frag; no transpose) ---
        unsigned ph[2][4][2];
#pragma unroll
        for (int mi = 0; mi < 2; mi++) {
#pragma unroll
            for (int j = 0; j < 4; j++) {
                float2 f0, f1;
                ph[mi][j][0] = exp2pk(s[mi][j][0] * L2E, s[mi][j][1] * L2E, f0);
                ph[mi][j][1] = exp2pk(s[mi][j][2] * L2E, s[mi][j][3] * L2E, f1);
                lacc[mi][0] += f0.x + f0.y;
                lacc[mi][1] += f1.x + f1.y;
            }
        }

        // --- O += P @ V : fp16 mma, contract own 32 keys x all 64 dims ---
#pragma unroll
        for (int t16 = 0; t16 < 2; t16++) {
            int kr = wk2 * 32 + t16 * 16 + ((lm & 1) ? 8 : 0) + lr;
#pragma unroll
            for (int np = 0; np < 4; np++) {
                unsigned bb[4];
                ldsm4t(bb, &Vt[kr * VLD + np * 16 + ((lm & 2) ? 8 : 0)]);
#pragma unroll
                for (int mi = 0; mi < 2; mi++) {
                    unsigned a[4] = { ph[mi][2 * t16][0], ph[mi][2 * t16][1],
                                      ph[mi][2 * t16 + 1][0], ph[mi][2 * t16 + 1][1] };
                    mma_f16(oacc[mi][2 * np],     a, bb[0], bb[1]);
                    mma_f16(oacc[mi][2 * np + 1], a, bb[2], bb[3]);
                }
            }
        }

        slot = (slot + 1) % 3;
    }

    // --- l: quad-reduce, publish per key-half ---
#pragma unroll
    for (int mi = 0; mi < 2; mi++)
#pragma unroll
        for (int ssb = 0; ssb < 2; ssb++) {
            lacc[mi][ssb] += __shfl_xor_sync(0xffffffffu, lacc[mi][ssb], 1);
            lacc[mi][ssb] += __shfl_xor_sync(0xffffffffu, lacc[mi][ssb], 2);
        }
    if (q4 == 0) {
#pragma unroll
        for (int mi = 0; mi < 2; mi++) {
            lsh[wk2 * 64 + qb + mi * 16 + gid]     = lacc[mi][0];
            lsh[wk2 * 64 + qb + mi * 16 + gid + 8] = lacc[mi][1];
        }
    }
    __syncthreads();   // last tile's reads done before Kb[0] reuse

    // --- O: reduce key-half partials via smem (reuse Kb[0]) ---
    float* Red = Kb[0];
    if (wk2 == 1) {
#pragma unroll
        for (int mi = 0; mi < 2; mi++) {
            int r = qb + mi * 16 + gid;
#pragma unroll
            for (int j = 0; j < 8; j++) {
                int c = j * 8 + 2 * q4;
                *(float2*)&Red[r * SLD + c] =
                    make_float2(oacc[mi][j][0], oacc[mi][j][1]);
                *(float2*)&Red[(r + 8) * SLD + c] =
                    make_float2(oacc[mi][j][2], oacc[mi][j][3]);
            }
        }
    }
    __syncthreads();
    if (wk2 == 0) {
#pragma unroll
        for (int mi = 0; mi < 2; mi++) {
            int row0 = qb + mi * 16 + gid;
            float il0 = 1.0f / (lsh[row0] + lsh[64 + row0]);
            float il1 = 1.0f / (lsh[row0 + 8] + lsh[64 + row0 + 8]);
            int r = b * LSEQ + q0 + row0;
#pragma unroll
            for (int j = 0; j < 8; j++) {
                int c = j * 8 + 2 * q4;
                float2 o0 = *(float2*)&Red[row0 * SLD + c];
                float2 o1 = *(float2*)&Red[(row0 + 8) * SLD + c];
                int gc = h * HD + c;
                *(float2*)&O[(size_t)r * CDIM + gc] =
                    make_float2((oacc[mi][j][0] + o0.x) * il0,
                                (oacc[mi][j][1] + o0.y) * il0);
                *(float2*)&O[(size_t)(r + 8) * CDIM + gc] =
                    make_float2((oacc[mi][j][2] + o1.x) * il1,
                                (oacc[mi][j][3] + o1.y) * il1);
            }
        }
    }
}

// ---------------------------------------------------------------------------
extern "C" void kernel_launch(void* const* d_in, const int* in_sizes, int n_in,
                              void* d_out, int out_size)
{
    const float* x   = (const float*)d_in[0];
    const float* wq  = (const float*)d_in[1];
    const float* wk  = (const float*)d_in[2];
    const float* wv  = (const float*)d_in[3];
    const float* wo  = (const float*)d_in[4];
    const float* qnw = (const float*)d_in[5];
    const float* knw = (const float*)d_in[6];
    float* out = (float*)d_out;

    float *pqkv, *pa;
    __half* pvh;
    cudaGetSymbolAddress((void**)&pqkv, g_qkv);
    cudaGetSymbolAddress((void**)&pvh, g_vh);
    cudaGetSymbolAddress((void**)&pa, g_attn);

    trig_kernel<<<LSEQ, 32>>>();
    gemm_qkv_kernel<<<dim3(QKVD / 64, BL / 64), 128>>>(x, wq, wk, wv, pqkv, pvh);

    norm_rope_kernel<<<(BL * 12 + 7) / 8, 256>>>(pqkv, qnw, knw);

    cudaFuncSetAttribute(attn_kernel, cudaFuncAttributeMaxDynamicSharedMemorySize,
                         (int)ATTN_SMEM);
    attn_kernel<<<dim3(LSEQ / 64, NH, BATCH), 128, ATTN_SMEM>>>(pqkv, pvh, pa);

    gemm_out_kernel<<<dim3(CDIM / 64, BL / 64), 128>>>(pa, wo, out);
}